// round 8
// baseline (speedup 1.0000x reference)
#include <cuda_runtime.h>
#include <cuda_bf16.h>
#include <math.h>

// Problem constants
#define Hdim   3584
#define Bb     8
#define NH     28
#define KVH    4
#define GS     7
#define HD     128
#define MB     16
#define BSZ    256
#define Rr     32          // B*KVH
#define QKVROWS 4608       // 3584 q + 512 k + 512 v
#define SCALE  0.08838834764831845f
#define NEG_INF (-1e30f)
#define NSPLIT 7           // column splits (3584 / 512)

// -------- scratch (device globals, no allocation) --------
__device__ float g_qkvp[NSPLIT * Bb * QKVROWS]; // qkv partials [y][b][vrow]
__device__ float g_part[Rr * MB * GS * HD];     // per-chunk partial PV sums
__device__ float g_ml[Rr * MB * GS * 2];        // per-chunk (m, l)
__device__ float g_attn[Bb * Hdim];             // attention output pre O-proj

// ============================================================
// GEMV core: warp = 4 rows x 512-col slice (y), 8 batches.
// No manual prefetch; <=64 regs so 4 blocks (32 warps) fit per
// SM — latency hiding via warp count, not per-warp MLP.
// ============================================================
__device__ __forceinline__ void gemv4x8(const float4* __restrict__ x4,
                                        const float4* __restrict__ w40,
                                        const float4* __restrict__ w41,
                                        const float4* __restrict__ w42,
                                        const float4* __restrict__ w43,
                                        int y, int lane, float acc[4][8]) {
    const int cb = y * 128 + lane;
#pragma unroll
    for (int u = 0; u < 4; u++) {
        const int c4 = cb + u * 32;
        const float4 w0 = w40[c4];
        const float4 w1 = w41[c4];
        const float4 w2 = w42[c4];
        const float4 w3 = w43[c4];
#pragma unroll
        for (int b = 0; b < 8; b++) {
            const float4 xv = x4[b * 896 + c4];
            acc[0][b] += w0.x * xv.x + w0.y * xv.y + w0.z * xv.z + w0.w * xv.w;
            acc[1][b] += w1.x * xv.x + w1.y * xv.y + w1.z * xv.z + w1.w * xv.w;
            acc[2][b] += w2.x * xv.x + w2.y * xv.y + w2.z * xv.z + w2.w * xv.w;
            acc[3][b] += w3.x * xv.x + w3.y * xv.y + w3.z * xv.z + w3.w * xv.w;
        }
    }
#pragma unroll
    for (int r = 0; r < 4; r++)
#pragma unroll
        for (int b = 0; b < 8; b++) {
#pragma unroll
            for (int off = 16; off; off >>= 1)
                acc[r][b] += __shfl_xor_sync(0xffffffffu, acc[r][b], off);
        }
}

// Fused QKV projection. grid (144, 7), 256 threads.
__global__ __launch_bounds__(256, 4) void qkv_gemv(
    const float* __restrict__ hid,
    const float* __restrict__ q_w, const float* __restrict__ q_b,
    const float* __restrict__ k_w, const float* __restrict__ k_b,
    const float* __restrict__ v_w, const float* __restrict__ v_b) {
    const int t = threadIdx.x;
    const int lane = t & 31;
    const int warp = t >> 5;
    const int y = blockIdx.y;
    const int rbase = blockIdx.x * 32 + warp * 4;   // virtual row base

    const float* W; const float* bias; int wrow;
    if (rbase < 3584)      { W = q_w; bias = q_b; wrow = rbase; }
    else if (rbase < 4096) { W = k_w; bias = k_b; wrow = rbase - 3584; }
    else                   { W = v_w; bias = v_b; wrow = rbase - 4096; }

    const float4* w40 = (const float4*)(W + (size_t)(wrow + 0) * Hdim);
    const float4* w41 = (const float4*)(W + (size_t)(wrow + 1) * Hdim);
    const float4* w42 = (const float4*)(W + (size_t)(wrow + 2) * Hdim);
    const float4* w43 = (const float4*)(W + (size_t)(wrow + 3) * Hdim);

    float acc[4][8];
#pragma unroll
    for (int r = 0; r < 4; r++)
#pragma unroll
        for (int b = 0; b < 8; b++) acc[r][b] = 0.f;

    gemv4x8((const float4*)hid, w40, w41, w42, w43, y, lane, acc);

    if (lane == 0) {
#pragma unroll
        for (int r = 0; r < 4; r++) {
            const float bv = (y == 0) ? bias[wrow + r] : 0.f;
#pragma unroll
            for (int b = 0; b < 8; b++)
                g_qkvp[(size_t)(y * 8 + b) * QKVROWS + rbase + r] = acc[r][b] + bv;
        }
    }
}

// O projection. grid (112, 7), 256 threads. atomicAdd into out
// (zeroed by attn_combine, which runs before on the same stream).
__global__ __launch_bounds__(256, 4) void o_gemv(const float* __restrict__ o_w,
                                                 float* __restrict__ out) {
    const int t = threadIdx.x;
    const int lane = t & 31;
    const int warp = t >> 5;
    const int y = blockIdx.y;
    const int rbase = blockIdx.x * 32 + warp * 4;

    const float4* w40 = (const float4*)(o_w + (size_t)(rbase + 0) * Hdim);
    const float4* w41 = (const float4*)(o_w + (size_t)(rbase + 1) * Hdim);
    const float4* w42 = (const float4*)(o_w + (size_t)(rbase + 2) * Hdim);
    const float4* w43 = (const float4*)(o_w + (size_t)(rbase + 3) * Hdim);

    float acc[4][8];
#pragma unroll
    for (int r = 0; r < 4; r++)
#pragma unroll
        for (int b = 0; b < 8; b++) acc[r][b] = 0.f;

    gemv4x8((const float4*)g_attn, w40, w41, w42, w43, y, lane, acc);

    if (lane == 0) {
#pragma unroll
        for (int r = 0; r < 4; r++)
#pragma unroll
            for (int b = 0; b < 8; b++)
                atomicAdd(&out[(size_t)b * Hdim + rbase + r], acc[r][b]);
    }
}

// helper: sum qkv partials for (batch b, virtual row vr)
__device__ __forceinline__ float qkv_sum(int b, int vr) {
    float s = 0.f;
#pragma unroll
    for (int yy = 0; yy < NSPLIT; yy++)
        s += g_qkvp[(size_t)(yy * 8 + b) * QKVROWS + vr];
    return s;
}

// ============================================================
// Attention partial (flash-decode split-K) with fused RoPE.
// grid = (16 chunks, 32 rows), 256 threads, dynamic smem.
// ============================================================
#define KROW 129
#define SMEM_ATTN ((16512 + 896 + 1792 + 128 + 128 + 896) * 4)

__global__ __launch_bounds__(256, 2) void attn_partial(
        const float* __restrict__ k_pool,
        const float* __restrict__ v_pool,
        const int* __restrict__ block_table,
        const int* __restrict__ cache_seqlens,
        const float* __restrict__ cos_,
        const float* __restrict__ sin_) {
    const int c = blockIdx.x;
    const int r = blockIdx.y;
    const int seqlen = cache_seqlens[r];
    const int base = c * BSZ;
    if (base >= seqlen) return;

    extern __shared__ float sm[];
    float* ks     = sm;               // [128][129] staged K half-chunk
    float* q_s    = sm + 16512;       // [7][128] rope'd q
    float* p_s    = q_s + 896;        // [7][256]
    float* knew_s = p_s + 1792;       // [128]
    float* vnew_s = knew_s + 128;     // [128]
    float* acc2_s = vnew_s + 128;     // [7][128]

    const int nvalid = min(BSZ, seqlen - base);
    const int pos = seqlen - 1;
    const int jpos = pos - base;
    const int b = r >> 2;
    const int kvh = r & 3;
    const int blk = block_table[r * MB + c];
    const float* __restrict__ K = k_pool + (size_t)blk * BSZ * HD;
    const float* __restrict__ V = v_pool + (size_t)blk * BSZ * HD;

    const int t = threadIdx.x;
    const float* cb = cos_ + b * HD;
    const float* sb = sin_ + b * HD;

    // ---- build q (7 heads, rope), k_new (rope), v_new from qkv partials ----
    {
        const int qvbase = kvh * GS * HD;
        for (int i = t; i < GS * 64; i += 256) {
            const int g = i >> 6;
            const int d = i & 63;
            const float cc = cb[d], ss = sb[d];
            const float a  = qkv_sum(b, qvbase + g * HD + d);
            const float b2 = qkv_sum(b, qvbase + g * HD + d + 64);
            q_s[g * HD + d]      = a * cc - b2 * ss;
            q_s[g * HD + d + 64] = b2 * cc + a * ss;
        }
        if (t < 64) {   // k_new rope pairs
            const int vr = 3584 + kvh * HD + t;
            const float cc = cb[t], ss = sb[t];
            const float a  = qkv_sum(b, vr);
            const float b2 = qkv_sum(b, vr + 64);
            knew_s[t]      = a * cc - b2 * ss;
            knew_s[t + 64] = b2 * cc + a * ss;
        } else if (t < 192) {  // v_new plain
            const int d = t - 64;
            vnew_s[d] = qkv_sum(b, 4096 + kvh * HD + d);
        }
    }

    // ---- phase 1: QK scores via staged smem halves ----
    const int jl = t & 127;
    const int hh = t >> 7;
    const bool valid_tok = (t < nvalid);
    float sc[GS];
#pragma unroll
    for (int g = 0; g < GS; g++) sc[g] = 0.f;

    for (int h = 0; h < 2; h++) {
        const int hbase = h * 128;
        if (hbase >= nvalid) break;
        __syncthreads();   // prev-half compute done / q+knew ready
        const float* Ksrc = K + (size_t)hbase * HD;
#pragma unroll 8
        for (int ii = 0; ii < 64; ii++) {
            const int w_idx = t + ii * 256;
            ks[(w_idx >> 7) * KROW + (w_idx & 127)] = Ksrc[w_idx];
        }
        __syncthreads();
        if (t < HD && jpos >= hbase && jpos < hbase + 128)
            ks[(jpos - hbase) * KROW + t] = knew_s[t];
        __syncthreads();
        if (hh == h && valid_tok) {
            const float* krow = ks + jl * KROW;
            const float4* q4 = (const float4*)q_s;
#pragma unroll 4
            for (int u = 0; u < 32; u++) {
                const float k0 = krow[4 * u + 0];
                const float k1 = krow[4 * u + 1];
                const float k2 = krow[4 * u + 2];
                const float k3 = krow[4 * u + 3];
#pragma unroll
                for (int g = 0; g < GS; g++) {
                    const float4 qv = q4[g * 32 + u];
                    sc[g] += k0 * qv.x + k1 * qv.y + k2 * qv.z + k3 * qv.w;
                }
            }
        }
    }

    // ---- phase 2: softmax, warp per head ----
#pragma unroll
    for (int g = 0; g < GS; g++)
        p_s[g * 256 + t] = valid_tok ? sc[g] * SCALE : NEG_INF;
    __syncthreads();

    const int lane = t & 31, warp = t >> 5;
    const int rc = r * MB + c;
    if (warp < GS) {
        const int g = warp;
        float v[8];
#pragma unroll
        for (int i = 0; i < 8; i++) v[i] = p_s[g * 256 + lane + i * 32];
        float m = v[0];
#pragma unroll
        for (int i = 1; i < 8; i++) m = fmaxf(m, v[i]);
#pragma unroll
        for (int off = 16; off; off >>= 1)
            m = fmaxf(m, __shfl_xor_sync(0xffffffffu, m, off));
        float l = 0.f;
#pragma unroll
        for (int i = 0; i < 8; i++) {
            const float e = __expf(v[i] - m);
            p_s[g * 256 + lane + i * 32] = e;
            l += e;
        }
#pragma unroll
        for (int off = 16; off; off >>= 1)
            l += __shfl_xor_sync(0xffffffffu, l, off);
        if (lane == 0) {
            g_ml[rc * (GS * 2) + g * 2 + 0] = m;
            g_ml[rc * (GS * 2) + g * 2 + 1] = l;
        }
    }
    __syncthreads();

    // ---- phase 3: PV, thread = dim, tokens split across halves ----
    const int d = t & 127;
    const int half = t >> 7;
    const int j0 = half * 128;
    float acc[GS];
#pragma unroll
    for (int g = 0; g < GS; g++) acc[g] = 0.f;
    const int jend = min(128, nvalid - j0);
    for (int jj = 0; jj < jend; jj++) {
        const int jt = j0 + jj;
        const float vv = (jt == jpos) ? vnew_s[d] : V[(size_t)jt * HD + d];
#pragma unroll
        for (int g = 0; g < GS; g++) acc[g] += p_s[g * 256 + jt] * vv;
    }
    if (half == 1) {
#pragma unroll
        for (int g = 0; g < GS; g++) acc2_s[g * 128 + d] = acc[g];
    }
    __syncthreads();
    if (half == 0) {
        float* outp = g_part + (size_t)rc * (GS * HD);
#pragma unroll
        for (int g = 0; g < GS; g++)
            outp[g * HD + d] = acc[g] + acc2_s[g * 128 + d];
    }
}

// ============================================================
// Combine split-K partials + zero the final output buffer for
// o_gemv's atomic accumulation. grid = (GS, Rr), 128 threads.
// ============================================================
__global__ void attn_combine(const int* __restrict__ cache_seqlens,
                             float* __restrict__ out) {
    const int g = blockIdx.x;
    const int r = blockIdx.y;
    const int d = threadIdx.x;

    // zero out[] : 224 blocks x 128 threads == 28672 elements exactly
    out[(blockIdx.y * GS + blockIdx.x) * 128 + d] = 0.f;

    const int seqlen = cache_seqlens[r];
    const int nc = (seqlen + BSZ - 1) >> 8;

    float M = NEG_INF;
    for (int c = 0; c < nc; c++)
        M = fmaxf(M, g_ml[(r * MB + c) * (GS * 2) + g * 2]);
    float L = 0.f, acc = 0.f;
    for (int c = 0; c < nc; c++) {
        const int rc = r * MB + c;
        const float m = g_ml[rc * (GS * 2) + g * 2 + 0];
        const float l = g_ml[rc * (GS * 2) + g * 2 + 1];
        const float w = __expf(m - M);
        L += l * w;
        acc += w * g_part[(size_t)rc * (GS * HD) + g * HD + d];
    }
    const int b = r >> 2, kvh = r & 3;
    g_attn[(size_t)b * Hdim + (kvh * GS + g) * HD + d] = acc / L;
}

// ============================================================
extern "C" void kernel_launch(void* const* d_in, const int* in_sizes, int n_in,
                              void* d_out, int out_size) {
    const float* hid  = (const float*)d_in[0];
    const float* cosw = (const float*)d_in[1];
    const float* sinw = (const float*)d_in[2];
    const float* q_w  = (const float*)d_in[3];
    const float* q_b  = (const float*)d_in[4];
    const float* k_w  = (const float*)d_in[5];
    const float* k_b  = (const float*)d_in[6];
    const float* v_w  = (const float*)d_in[7];
    const float* v_b  = (const float*)d_in[8];
    const float* o_w  = (const float*)d_in[9];
    const float* k_pool = (const float*)d_in[10];
    const float* v_pool = (const float*)d_in[11];
    const int* block_table   = (const int*)d_in[12];
    const int* cache_seqlens = (const int*)d_in[13];
    float* out = (float*)d_out;

    cudaFuncSetAttribute(attn_partial, cudaFuncAttributeMaxDynamicSharedMemorySize, SMEM_ATTN);

    // Fused QKV projections: 4608 rows / 32 per block, 7 col-slices
    qkv_gemv<<<dim3(144, NSPLIT), 256>>>(hid, q_w, q_b, k_w, k_b, v_w, v_b);
    // flash-decode partials (rope + qkv-partial reduce fused inside)
    attn_partial<<<dim3(MB, Rr), 256, SMEM_ATTN>>>(k_pool, v_pool, block_table,
                                                   cache_seqlens, cosw, sinw);
    // combine + zero out
    attn_combine<<<dim3(GS, Rr), 128>>>(cache_seqlens, out);
    // O projection: 3584 rows / 32 per block, 7 col-slices, atomic accumulate
    o_gemv<<<dim3(112, NSPLIT), 256>>>(o_w, out);
}

// round 9
// speedup vs baseline: 1.1234x; 1.1234x over previous
#include <cuda_runtime.h>
#include <cuda_bf16.h>
#include <math.h>

// Problem constants
#define Hdim   3584
#define Bb     8
#define NH     28
#define KVH    4
#define GS     7
#define HD     128
#define MB     16
#define BSZ    256
#define Rr     32          // B*KVH
#define QKVROWS 4608       // 3584 q + 512 k + 512 v
#define SCALE  0.08838834764831845f
#define NEG_INF (-1e30f)
#define NSPLIT 7           // column splits (3584 / 512)

// -------- scratch (device globals, no allocation) --------
__device__ float g_qkvp[NSPLIT * Bb * QKVROWS]; // qkv partials [y][b][vrow]
__device__ float g_part[Rr * MB * GS * HD];     // per-chunk partial PV sums
__device__ float g_ml[Rr * MB * GS * 2];        // per-chunk (m, l)
__device__ float g_attn[Bb * Hdim];             // attention output pre O-proj

// ============================================================
// GEMV core (R7-proven): warp = 4 rows x 512-col slice, 8 batches.
// Double-buffered weight prefetch at 128-reg budget.
// ============================================================
__device__ __forceinline__ void gemv4x8_pipe(const float4* __restrict__ x4,
                                             const float4* __restrict__ w40,
                                             const float4* __restrict__ w41,
                                             const float4* __restrict__ w42,
                                             const float4* __restrict__ w43,
                                             int y, int lane, float acc[4][8]) {
    const int cb = y * 128 + lane;
    float4 wc0 = w40[cb];
    float4 wc1 = w41[cb];
    float4 wc2 = w42[cb];
    float4 wc3 = w43[cb];

#pragma unroll
    for (int u = 0; u < 4; u++) {
        float4 wn0, wn1, wn2, wn3;
        if (u < 3) {
            const int cn = cb + (u + 1) * 32;
            wn0 = w40[cn];
            wn1 = w41[cn];
            wn2 = w42[cn];
            wn3 = w43[cn];
        }
        const int c4 = cb + u * 32;
#pragma unroll
        for (int b = 0; b < 8; b++) {
            const float4 xv = x4[b * 896 + c4];
            acc[0][b] += wc0.x * xv.x + wc0.y * xv.y + wc0.z * xv.z + wc0.w * xv.w;
            acc[1][b] += wc1.x * xv.x + wc1.y * xv.y + wc1.z * xv.z + wc1.w * xv.w;
            acc[2][b] += wc2.x * xv.x + wc2.y * xv.y + wc2.z * xv.z + wc2.w * xv.w;
            acc[3][b] += wc3.x * xv.x + wc3.y * xv.y + wc3.z * xv.z + wc3.w * xv.w;
        }
        if (u < 3) { wc0 = wn0; wc1 = wn1; wc2 = wn2; wc3 = wn3; }
    }

#pragma unroll
    for (int r = 0; r < 4; r++)
#pragma unroll
        for (int b = 0; b < 8; b++) {
#pragma unroll
            for (int off = 16; off; off >>= 1)
                acc[r][b] += __shfl_xor_sync(0xffffffffu, acc[r][b], off);
        }
}

// Fused QKV projection. grid (144, 7), 256 threads.
__global__ __launch_bounds__(256, 2) void qkv_gemv(
    const float* __restrict__ hid,
    const float* __restrict__ q_w, const float* __restrict__ q_b,
    const float* __restrict__ k_w, const float* __restrict__ k_b,
    const float* __restrict__ v_w, const float* __restrict__ v_b) {
    const int t = threadIdx.x;
    const int lane = t & 31;
    const int warp = t >> 5;
    const int y = blockIdx.y;
    const int rbase = blockIdx.x * 32 + warp * 4;   // virtual row base

    const float* W; const float* bias; int wrow;
    if (rbase < 3584)      { W = q_w; bias = q_b; wrow = rbase; }
    else if (rbase < 4096) { W = k_w; bias = k_b; wrow = rbase - 3584; }
    else                   { W = v_w; bias = v_b; wrow = rbase - 4096; }

    const float4* w40 = (const float4*)(W + (size_t)(wrow + 0) * Hdim);
    const float4* w41 = (const float4*)(W + (size_t)(wrow + 1) * Hdim);
    const float4* w42 = (const float4*)(W + (size_t)(wrow + 2) * Hdim);
    const float4* w43 = (const float4*)(W + (size_t)(wrow + 3) * Hdim);

    float acc[4][8];
#pragma unroll
    for (int r = 0; r < 4; r++)
#pragma unroll
        for (int b = 0; b < 8; b++) acc[r][b] = 0.f;

    gemv4x8_pipe((const float4*)hid, w40, w41, w42, w43, y, lane, acc);

    if (lane == 0) {
#pragma unroll
        for (int r = 0; r < 4; r++) {
            const float bv = (y == 0) ? bias[wrow + r] : 0.f;
#pragma unroll
            for (int b = 0; b < 8; b++)
                g_qkvp[(size_t)(y * 8 + b) * QKVROWS + rbase + r] = acc[r][b] + bv;
        }
    }
}

// O projection. grid (112, 7), 256 threads.
// Atomic accumulate into out (zeroed earlier by attn_combine).
__global__ __launch_bounds__(256, 2) void o_gemv(const float* __restrict__ o_w,
                                                 float* __restrict__ out) {
    const int t = threadIdx.x;
    const int lane = t & 31;
    const int warp = t >> 5;
    const int y = blockIdx.y;
    const int rbase = blockIdx.x * 32 + warp * 4;

    const float4* w40 = (const float4*)(o_w + (size_t)(rbase + 0) * Hdim);
    const float4* w41 = (const float4*)(o_w + (size_t)(rbase + 1) * Hdim);
    const float4* w42 = (const float4*)(o_w + (size_t)(rbase + 2) * Hdim);
    const float4* w43 = (const float4*)(o_w + (size_t)(rbase + 3) * Hdim);

    float acc[4][8];
#pragma unroll
    for (int r = 0; r < 4; r++)
#pragma unroll
        for (int b = 0; b < 8; b++) acc[r][b] = 0.f;

    gemv4x8_pipe((const float4*)g_attn, w40, w41, w42, w43, y, lane, acc);

    if (lane == 0) {
#pragma unroll
        for (int r = 0; r < 4; r++)
#pragma unroll
            for (int b = 0; b < 8; b++)
                atomicAdd(&out[(size_t)b * Hdim + rbase + r], acc[r][b]);
    }
}

// helper: sum qkv partials for (batch b, virtual row vr)
__device__ __forceinline__ float qkv_sum(int b, int vr) {
    float s = 0.f;
#pragma unroll
    for (int yy = 0; yy < NSPLIT; yy++)
        s += g_qkvp[(size_t)(yy * 8 + b) * QKVROWS + vr];
    return s;
}

// ============================================================
// Attention partial (flash-decode split-K) with fused RoPE.
// grid = (16 chunks, 32 rows), 256 threads, dynamic smem.
// ============================================================
#define KROW 129
#define SMEM_ATTN ((16512 + 896 + 1792 + 128 + 128 + 896) * 4)

__global__ __launch_bounds__(256, 2) void attn_partial(
        const float* __restrict__ k_pool,
        const float* __restrict__ v_pool,
        const int* __restrict__ block_table,
        const int* __restrict__ cache_seqlens,
        const float* __restrict__ cos_,
        const float* __restrict__ sin_) {
    const int c = blockIdx.x;
    const int r = blockIdx.y;
    const int seqlen = cache_seqlens[r];
    const int base = c * BSZ;
    if (base >= seqlen) return;

    extern __shared__ float sm[];
    float* ks     = sm;               // [128][129] staged K half-chunk
    float* q_s    = sm + 16512;       // [7][128] rope'd q
    float* p_s    = q_s + 896;        // [7][256]
    float* knew_s = p_s + 1792;       // [128]
    float* vnew_s = knew_s + 128;     // [128]
    float* acc2_s = vnew_s + 128;     // [7][128]

    const int nvalid = min(BSZ, seqlen - base);
    const int pos = seqlen - 1;
    const int jpos = pos - base;
    const int b = r >> 2;
    const int kvh = r & 3;
    const int blk = block_table[r * MB + c];
    const float* __restrict__ K = k_pool + (size_t)blk * BSZ * HD;
    const float* __restrict__ V = v_pool + (size_t)blk * BSZ * HD;

    const int t = threadIdx.x;
    const float* cb = cos_ + b * HD;
    const float* sb = sin_ + b * HD;

    // ---- build q (7 heads, rope), k_new (rope), v_new from qkv partials ----
    {
        const int qvbase = kvh * GS * HD;
        for (int i = t; i < GS * 64; i += 256) {
            const int g = i >> 6;
            const int d = i & 63;
            const float cc = cb[d], ss = sb[d];
            const float a  = qkv_sum(b, qvbase + g * HD + d);
            const float b2 = qkv_sum(b, qvbase + g * HD + d + 64);
            q_s[g * HD + d]      = a * cc - b2 * ss;
            q_s[g * HD + d + 64] = b2 * cc + a * ss;
        }
        if (t < 64) {   // k_new rope pairs
            const int vr = 3584 + kvh * HD + t;
            const float cc = cb[t], ss = sb[t];
            const float a  = qkv_sum(b, vr);
            const float b2 = qkv_sum(b, vr + 64);
            knew_s[t]      = a * cc - b2 * ss;
            knew_s[t + 64] = b2 * cc + a * ss;
        } else if (t < 192) {  // v_new plain
            const int d = t - 64;
            vnew_s[d] = qkv_sum(b, 4096 + kvh * HD + d);
        }
    }

    // ---- phase 1: QK scores via staged smem halves ----
    const int jl = t & 127;
    const int hh = t >> 7;
    const bool valid_tok = (t < nvalid);
    float sc[GS];
#pragma unroll
    for (int g = 0; g < GS; g++) sc[g] = 0.f;

    for (int h = 0; h < 2; h++) {
        const int hbase = h * 128;
        if (hbase >= nvalid) break;
        __syncthreads();   // prev-half compute done / q+knew ready
        // stage 128 rows, coalesced; substitute rope'd new-token row inline
        const int jloc = jpos - hbase;       // in [0,128) iff new token in this half
        const float* Ksrc = K + (size_t)hbase * HD;
#pragma unroll 8
        for (int ii = 0; ii < 64; ii++) {
            const int w_idx = t + ii * 256;
            const int row = w_idx >> 7;
            const int col = w_idx & 127;
            float val = Ksrc[w_idx];
            if (row == jloc) val = knew_s[col];
            ks[row * KROW + col] = val;
        }
        __syncthreads();
        if (hh == h && valid_tok) {
            const float* krow = ks + jl * KROW;
            const float4* q4 = (const float4*)q_s;
#pragma unroll 4
            for (int u = 0; u < 32; u++) {
                const float k0 = krow[4 * u + 0];
                const float k1 = krow[4 * u + 1];
                const float k2 = krow[4 * u + 2];
                const float k3 = krow[4 * u + 3];
#pragma unroll
                for (int g = 0; g < GS; g++) {
                    const float4 qv = q4[g * 32 + u];
                    sc[g] += k0 * qv.x + k1 * qv.y + k2 * qv.z + k3 * qv.w;
                }
            }
        }
    }

    // ---- phase 2: softmax, warp per head ----
#pragma unroll
    for (int g = 0; g < GS; g++)
        p_s[g * 256 + t] = valid_tok ? sc[g] * SCALE : NEG_INF;
    __syncthreads();

    const int lane = t & 31, warp = t >> 5;
    const int rc = r * MB + c;
    if (warp < GS) {
        const int g = warp;
        float v[8];
#pragma unroll
        for (int i = 0; i < 8; i++) v[i] = p_s[g * 256 + lane + i * 32];
        float m = v[0];
#pragma unroll
        for (int i = 1; i < 8; i++) m = fmaxf(m, v[i]);
#pragma unroll
        for (int off = 16; off; off >>= 1)
            m = fmaxf(m, __shfl_xor_sync(0xffffffffu, m, off));
        float l = 0.f;
#pragma unroll
        for (int i = 0; i < 8; i++) {
            const float e = __expf(v[i] - m);
            p_s[g * 256 + lane + i * 32] = e;
            l += e;
        }
#pragma unroll
        for (int off = 16; off; off >>= 1)
            l += __shfl_xor_sync(0xffffffffu, l, off);
        if (lane == 0) {
            g_ml[rc * (GS * 2) + g * 2 + 0] = m;
            g_ml[rc * (GS * 2) + g * 2 + 1] = l;
        }
    }
    __syncthreads();

    // ---- phase 3: PV, thread = dim, tokens split across halves.
    //      p read via LDS.128 broadcast (4 tokens/inst); 4 batched V LDGs.
    //      p_s is 0 beyond nvalid, so 4-rounded overrun contributes 0.
    const int d = t & 127;
    const int half = t >> 7;
    const int j0 = half * 128;
    float acc[GS];
#pragma unroll
    for (int g = 0; g < GS; g++) acc[g] = 0.f;
    const int jend = min(128, nvalid - j0);
    if (jend > 0) {
        const int jend4 = (jend + 3) & ~3;
        for (int jj = 0; jj < jend4; jj += 4) {
            const int jt = j0 + jj;
            const float vv0 = (jt + 0 == jpos) ? vnew_s[d] : V[(size_t)(jt + 0) * HD + d];
            const float vv1 = (jt + 1 == jpos) ? vnew_s[d] : V[(size_t)(jt + 1) * HD + d];
            const float vv2 = (jt + 2 == jpos) ? vnew_s[d] : V[(size_t)(jt + 2) * HD + d];
            const float vv3 = (jt + 3 == jpos) ? vnew_s[d] : V[(size_t)(jt + 3) * HD + d];
            float4 p4[GS];
#pragma unroll
            for (int g = 0; g < GS; g++)
                p4[g] = *(const float4*)(p_s + g * 256 + jt);
#pragma unroll
            for (int g = 0; g < GS; g++)
                acc[g] += p4[g].x * vv0 + p4[g].y * vv1 + p4[g].z * vv2 + p4[g].w * vv3;
        }
    }
    if (half == 1) {
#pragma unroll
        for (int g = 0; g < GS; g++) acc2_s[g * 128 + d] = acc[g];
    }
    __syncthreads();
    if (half == 0) {
        float* outp = g_part + (size_t)rc * (GS * HD);
#pragma unroll
        for (int g = 0; g < GS; g++)
            outp[g * HD + d] = acc[g] + acc2_s[g * 128 + d];
    }
}

// ============================================================
// Combine split-K partials + zero final out for o_gemv atomics.
// grid = (GS, Rr), 128 threads.  224*128 == 28672 == out size.
// ============================================================
__global__ void attn_combine(const int* __restrict__ cache_seqlens,
                             float* __restrict__ out) {
    const int g = blockIdx.x;
    const int r = blockIdx.y;
    const int d = threadIdx.x;

    out[(blockIdx.y * GS + blockIdx.x) * 128 + d] = 0.f;

    const int seqlen = cache_seqlens[r];
    const int nc = (seqlen + BSZ - 1) >> 8;

    float M = NEG_INF;
    for (int c = 0; c < nc; c++)
        M = fmaxf(M, g_ml[(r * MB + c) * (GS * 2) + g * 2]);
    float L = 0.f, acc = 0.f;
    for (int c = 0; c < nc; c++) {
        const int rc = r * MB + c;
        const float m = g_ml[rc * (GS * 2) + g * 2 + 0];
        const float l = g_ml[rc * (GS * 2) + g * 2 + 1];
        const float w = __expf(m - M);
        L += l * w;
        acc += w * g_part[(size_t)rc * (GS * HD) + g * HD + d];
    }
    const int b = r >> 2, kvh = r & 3;
    g_attn[(size_t)b * Hdim + (kvh * GS + g) * HD + d] = acc / L;
}

// ============================================================
extern "C" void kernel_launch(void* const* d_in, const int* in_sizes, int n_in,
                              void* d_out, int out_size) {
    const float* hid  = (const float*)d_in[0];
    const float* cosw = (const float*)d_in[1];
    const float* sinw = (const float*)d_in[2];
    const float* q_w  = (const float*)d_in[3];
    const float* q_b  = (const float*)d_in[4];
    const float* k_w  = (const float*)d_in[5];
    const float* k_b  = (const float*)d_in[6];
    const float* v_w  = (const float*)d_in[7];
    const float* v_b  = (const float*)d_in[8];
    const float* o_w  = (const float*)d_in[9];
    const float* k_pool = (const float*)d_in[10];
    const float* v_pool = (const float*)d_in[11];
    const int* block_table   = (const int*)d_in[12];
    const int* cache_seqlens = (const int*)d_in[13];
    float* out = (float*)d_out;

    cudaFuncSetAttribute(attn_partial, cudaFuncAttributeMaxDynamicSharedMemorySize, SMEM_ATTN);

    // Fused QKV projections: 4608 rows / 32 per block, 7 col-slices
    qkv_gemv<<<dim3(144, NSPLIT), 256>>>(hid, q_w, q_b, k_w, k_b, v_w, v_b);
    // flash-decode partials (rope + qkv-partial reduce fused inside)
    attn_partial<<<dim3(MB, Rr), 256, SMEM_ATTN>>>(k_pool, v_pool, block_table,
                                                   cache_seqlens, cosw, sinw);
    // combine + zero out
    attn_combine<<<dim3(GS, Rr), 128>>>(cache_seqlens, out);
    // O projection: 3584 rows / 32 per block, 7 col-slices, atomic accumulate
    o_gemv<<<dim3(112, NSPLIT), 256>>>(o_w, out);
}